// round 7
// baseline (speedup 1.0000x reference)
#include <cuda_runtime.h>
#include <cstdint>

// Inputs (metadata order):
//   d_in[0] state           float32 [B, A, N, 3]
//   d_in[1] nodes_coords    float32 [P, 2]
//   d_in[2] adj             float32 [P, N]
//   d_in[3] node_last_visit int32   [B, A]
//   d_in[4] patrol_index    int32   [P]
// Output: float32 [B, A, N, 6]

#define RPC 4  // rows per CTA

__global__ __launch_bounds__(128)
void policy_gather_kernel(const float* __restrict__ state,
                          const float* __restrict__ coords,
                          const float* __restrict__ adj,
                          const int*   __restrict__ nlv,
                          const int*   __restrict__ pidx,
                          float* __restrict__ out,
                          int N, int BA) {
    extern __shared__ __align__(16) float s_tiles[];   // RPC * N*6 floats

    const int base = blockIdx.x * RPC;
    const int t    = threadIdx.x;
    const int tileN = N * 6;

    // Batched row-constant gathers: 4 independent chains in flight (MLP=4).
    int   v[RPC], ix[RPC];
    float zx[RPC], zy[RPC];
    #pragma unroll
    for (int r = 0; r < RPC; ++r) {
        const int rr = (base + r < BA) ? (base + r) : (BA - 1);
        v[r] = __ldg(nlv + rr);
    }
    #pragma unroll
    for (int r = 0; r < RPC; ++r) ix[r] = __ldg(pidx + v[r]);
    #pragma unroll
    for (int r = 0; r < RPC; ++r) {
        zx[r] = __ldg(coords + 2 * v[r]);
        zy[r] = __ldg(coords + 2 * v[r] + 1);
    }

    const bool okA = ((((uintptr_t)state) | ((uintptr_t)adj)) & 7) == 0;
    const unsigned bytes = (unsigned)(tileN * sizeof(float));
    const bool okTMA = ((((uintptr_t)out) & 0xF) == 0) && ((bytes & 0xF) == 0)
                       && ((tileN & 3) == 0);

    #pragma unroll
    for (int r = 0; r < RPC; ++r) {
        const int row = base + r;
        const bool active = (row < BA);
        float* s_row = s_tiles + r * tileN;

        if (active) {
            const float* __restrict__ st = state + (size_t)row * N * 3;  // 8B aligned
            const float* __restrict__ ar = adj   + (size_t)ix[r] * N;    // 8B aligned

            if (okA) {
                // Phase 1: one thread per node pair.
                const int pairs = N >> 1;
                for (int p = t; p < pairs; p += blockDim.x) {
                    const float2 s01 = __ldcs(reinterpret_cast<const float2*>(st + 6 * p));
                    const float2 s23 = __ldcs(reinterpret_cast<const float2*>(st + 6 * p + 2));
                    const float2 s45 = __ldcs(reinterpret_cast<const float2*>(st + 6 * p + 4));
                    const float2 aa  = __ldg (reinterpret_cast<const float2*>(ar + 2 * p));

                    float4* d = reinterpret_cast<float4*>(s_row + 12 * p);
                    d[0] = make_float4(s01.x, s01.y, s23.x, zx[r]);
                    d[1] = make_float4(zy[r], aa.x,  s23.y, s45.x);
                    d[2] = make_float4(s45.y, zx[r], zy[r], aa.y);
                }
                if ((N & 1) && t == 0) {
                    const int n = N - 1;
                    float* d = s_row + 6 * n;
                    d[0] = st[3 * n + 0];
                    d[1] = st[3 * n + 1];
                    d[2] = st[3 * n + 2];
                    d[3] = zx[r];
                    d[4] = zy[r];
                    d[5] = ar[n];
                }
            } else {
                for (int n = t; n < N; n += blockDim.x) {
                    float* d = s_row + 6 * n;
                    d[0] = st[3 * n + 0];
                    d[1] = st[3 * n + 1];
                    d[2] = st[3 * n + 2];
                    d[3] = zx[r];
                    d[4] = zy[r];
                    d[5] = ar[n];
                }
            }
        }

        if (okTMA) {
            // Order generic smem writes before async-proxy read, then commit
            // this row's bulk store and move straight to the next row's gather.
            asm volatile("fence.proxy.async.shared::cta;" ::: "memory");
            __syncthreads();
            if (active && t == 0) {
                float* __restrict__ orow = out + (size_t)row * tileN;
                uint32_t saddr;
                asm("{ .reg .u64 tmp; cvta.to.shared.u64 tmp, %1; cvt.u32.u64 %0, tmp; }"
                    : "=r"(saddr) : "l"(s_row));
                asm volatile(
                    "cp.async.bulk.global.shared::cta.bulk_group [%0], [%1], %2;"
                    :: "l"(orow), "r"(saddr), "r"(bytes) : "memory");
                asm volatile("cp.async.bulk.commit_group;" ::: "memory");
            }
        } else {
            __syncthreads();
            if (active) {
                float* __restrict__ orow = out + (size_t)row * tileN;
                for (int j = t; j < tileN; j += blockDim.x) {
                    __stcs(orow + j, s_row[j]);
                }
            }
        }
    }

    // Drain all committed bulk stores before CTA exit.
    if (okTMA && t == 0) {
        asm volatile("cp.async.bulk.wait_group 0;" ::: "memory");
    }
}

extern "C" void kernel_launch(void* const* d_in, const int* in_sizes, int n_in,
                              void* d_out, int out_size) {
    const float* state  = (const float*)d_in[0];
    const float* coords = (const float*)d_in[1];
    const float* adj    = (const float*)d_in[2];
    const int*   nlv    = (const int*)d_in[3];
    const int*   pidx   = (const int*)d_in[4];
    float*       out    = (float*)d_out;

    const int BA = in_sizes[3];            // B * A rows
    const int P  = in_sizes[4];            // patrol nodes
    const int N  = in_sizes[2] / P;        // graph size (adj is [P, N])

    const int grid = (BA + RPC - 1) / RPC;
    const size_t smem = (size_t)RPC * N * 6 * sizeof(float);

    policy_gather_kernel<<<grid, 128, smem>>>(state, coords, adj, nlv, pidx, out, N, BA);
}

// round 8
// speedup vs baseline: 1.1097x; 1.1097x over previous
#include <cuda_runtime.h>
#include <cstdint>

// Inputs (metadata order):
//   d_in[0] state           float32 [B, A, N, 3]
//   d_in[1] nodes_coords    float32 [P, 2]
//   d_in[2] adj             float32 [P, N]
//   d_in[3] node_last_visit int32   [B, A]
//   d_in[4] patrol_index    int32   [P]
// Output: float32 [B, A, N, 6]

#define RPC 2  // rows per CTA (12KB smem: occupancy-neutral vs R6)

__global__ __launch_bounds__(128)
void policy_gather_kernel(const float* __restrict__ state,
                          const float* __restrict__ coords,
                          const float* __restrict__ adj,
                          const int*   __restrict__ nlv,
                          const int*   __restrict__ pidx,
                          float* __restrict__ out,
                          int N, int BA) {
    extern __shared__ __align__(16) float s_tiles[];   // RPC * N*6 floats

    const int base  = blockIdx.x * RPC;
    const int t     = threadIdx.x;
    const int tileN = N * 6;

    // Batched row-constant gathers (MLP=RPC on the dependent chain).
    int   v[RPC], ix[RPC];
    float zx[RPC], zy[RPC];
    #pragma unroll
    for (int r = 0; r < RPC; ++r) {
        const int rr = (base + r < BA) ? (base + r) : (BA - 1);
        v[r] = __ldg(nlv + rr);
    }
    #pragma unroll
    for (int r = 0; r < RPC; ++r) ix[r] = __ldg(pidx + v[r]);
    #pragma unroll
    for (int r = 0; r < RPC; ++r) {
        zx[r] = __ldg(coords + 2 * v[r]);
        zy[r] = __ldg(coords + 2 * v[r] + 1);
    }

    const bool okA = ((((uintptr_t)state) | ((uintptr_t)adj)) & 7) == 0;
    const unsigned bytes = (unsigned)(tileN * sizeof(float));
    const bool okTMA = ((((uintptr_t)out) & 0xF) == 0) && ((bytes & 0xF) == 0);

    #pragma unroll
    for (int r = 0; r < RPC; ++r) {
        const int row    = base + r;
        const bool active = (row < BA);
        float* s_row = s_tiles + r * tileN;

        if (active) {
            const float* __restrict__ st = state + (size_t)row * N * 3;  // 8B aligned
            const float* __restrict__ ar = adj   + (size_t)ix[r] * N;    // 8B aligned

            if (okA) {
                // Phase 1: one thread per node pair.
                // 3x LDG.64 (state) + 1x LDG.64 (adj) -> 3x STS.128.
                const int pairs = N >> 1;
                for (int p = t; p < pairs; p += blockDim.x) {
                    const float2 s01 = __ldcs(reinterpret_cast<const float2*>(st + 6 * p));
                    const float2 s23 = __ldcs(reinterpret_cast<const float2*>(st + 6 * p + 2));
                    const float2 s45 = __ldcs(reinterpret_cast<const float2*>(st + 6 * p + 4));
                    const float2 aa  = __ldg (reinterpret_cast<const float2*>(ar + 2 * p));

                    float4* d = reinterpret_cast<float4*>(s_row + 12 * p);
                    d[0] = make_float4(s01.x, s01.y, s23.x, zx[r]);
                    d[1] = make_float4(zy[r], aa.x,  s23.y, s45.x);
                    d[2] = make_float4(s45.y, zx[r], zy[r], aa.y);
                }
                if ((N & 1) && t == 0) {
                    const int n = N - 1;
                    float* d = s_row + 6 * n;
                    d[0] = st[3 * n + 0];
                    d[1] = st[3 * n + 1];
                    d[2] = st[3 * n + 2];
                    d[3] = zx[r];
                    d[4] = zy[r];
                    d[5] = ar[n];
                }
            } else {
                for (int n = t; n < N; n += blockDim.x) {
                    float* d = s_row + 6 * n;
                    d[0] = st[3 * n + 0];
                    d[1] = st[3 * n + 1];
                    d[2] = st[3 * n + 2];
                    d[3] = zx[r];
                    d[4] = zy[r];
                    d[5] = ar[n];
                }
            }
        }

        if (okTMA) {
            // Order generic smem writes before the async-proxy bulk read,
            // commit this row's store, then fall through to the next row's
            // gather while it drains.
            asm volatile("fence.proxy.async.shared::cta;" ::: "memory");
            __syncthreads();
            if (active && t == 0) {
                float* __restrict__ orow = out + (size_t)row * tileN;
                uint32_t saddr;
                asm("{ .reg .u64 tmp; cvta.to.shared.u64 tmp, %1; cvt.u32.u64 %0, tmp; }"
                    : "=r"(saddr) : "l"(s_row));
                asm volatile(
                    "cp.async.bulk.global.shared::cta.bulk_group [%0], [%1], %2;"
                    :: "l"(orow), "r"(saddr), "r"(bytes) : "memory");
                asm volatile("cp.async.bulk.commit_group;" ::: "memory");
            }
        } else {
            __syncthreads();
            if (active) {
                float* __restrict__ orow = out + (size_t)row * tileN;
                for (int j = t; j < tileN; j += blockDim.x) {
                    __stcs(orow + j, s_row[j]);
                }
            }
        }
    }

    // Drain all committed bulk stores before CTA exit (smem must stay valid).
    if (okTMA && t == 0) {
        asm volatile("cp.async.bulk.wait_group 0;" ::: "memory");
    }
}

extern "C" void kernel_launch(void* const* d_in, const int* in_sizes, int n_in,
                              void* d_out, int out_size) {
    const float* state  = (const float*)d_in[0];
    const float* coords = (const float*)d_in[1];
    const float* adj    = (const float*)d_in[2];
    const int*   nlv    = (const int*)d_in[3];
    const int*   pidx   = (const int*)d_in[4];
    float*       out    = (float*)d_out;

    const int BA = in_sizes[3];            // B * A rows
    const int P  = in_sizes[4];            // patrol nodes
    const int N  = in_sizes[2] / P;        // graph size (adj is [P, N])

    const int grid = (BA + RPC - 1) / RPC;
    const size_t smem = (size_t)RPC * N * 6 * sizeof(float);

    policy_gather_kernel<<<grid, 128, smem>>>(state, coords, adj, nlv, pidx, out, N, BA);
}